// round 4
// baseline (speedup 1.0000x reference)
#include <cuda_runtime.h>

#define BATCH 8
#define NPTS  4096
#define MPTS  2048
#define FDIM  64
#define KNBR  64
#define NG    (BATCH*MPTS)
#define CAP   256

// output segments (float32): x_out [NG,128] | pos_out [NG,3] | batch_out [NG]
#define XSEG   (NG*128)
#define PBASE  XSEG
#define BBASE  (XSEG + NG*3)
#define TOTSEG (BBASE + NG)

__device__ float g_q[NG*3];
__device__ int   g_nbr[NG*KNBR];
__device__ int   g_cnt[NG];

// ============================================================================
// 1) Farthest point sampling: one block per cloud, points in registers.
// ============================================================================
__global__ void __launch_bounds__(256)
fps_kernel(const float* __restrict__ pos, float* __restrict__ dout, int out_size)
{
    extern __shared__ float sp[];              // [NPTS*4]
    __shared__ float rd[8];
    __shared__ int   ri[8];
    __shared__ int   s_cur;

    const int b = blockIdx.x, tid = threadIdx.x;
    const int lane = tid & 31, w = tid >> 5;
    const float* pb = pos + (size_t)b * NPTS * 3;

    for (int i = tid; i < NPTS * 3; i += 256) {
        int p = i / 3, c = i - 3 * p;
        sp[4 * p + c] = pb[i];
    }
    if (tid == 0) s_cur = 0;
    __syncthreads();

    float px[16], py[16], pz[16], md[16];
#pragma unroll
    for (int j = 0; j < 16; j++) {
        int idx = j * 256 + tid;
        px[j] = sp[4 * idx]; py[j] = sp[4 * idx + 1]; pz[j] = sp[4 * idx + 2];
        md[j] = __int_as_float(0x7f800000);
    }

    if (tid == 0) {
        int g = b * MPTS;
        g_q[3*g] = sp[0]; g_q[3*g+1] = sp[1]; g_q[3*g+2] = sp[2];
        if (out_size >= BBASE) {
            dout[PBASE+3*g] = sp[0]; dout[PBASE+3*g+1] = sp[1]; dout[PBASE+3*g+2] = sp[2];
        }
        if (out_size >= TOTSEG) dout[BBASE+g] = (float)b;
    }

    const float4* sp4 = (const float4*)sp;

    for (int step = 1; step < MPTS; step++) {
        float4 L = sp4[s_cur];
        float bd = -1.0f; int bi = 0;
#pragma unroll
        for (int j = 0; j < 16; j++) {
            float dx = __fadd_rn(px[j], -L.x);
            float dy = __fadd_rn(py[j], -L.y);
            float dz = __fadd_rn(pz[j], -L.z);
            float d  = __fadd_rn(__fadd_rn(__fmul_rn(dx,dx), __fmul_rn(dy,dy)),
                                 __fmul_rn(dz,dz));
            float m = fminf(md[j], d);
            md[j] = m;
            if (m > bd) { bd = m; bi = j * 256 + tid; }
        }
#pragma unroll
        for (int off = 16; off >= 1; off >>= 1) {
            float od = __shfl_down_sync(0xffffffffu, bd, off);
            int   oi = __shfl_down_sync(0xffffffffu, bi, off);
            if (od > bd || (od == bd && oi < bi)) { bd = od; bi = oi; }
        }
        if (lane == 0) { rd[w] = bd; ri[w] = bi; }
        __syncthreads();
        if (w == 0) {
            float d2 = (lane < 8) ? rd[lane] : -2.0f;
            int   i2 = (lane < 8) ? ri[lane] : 0x7fffffff;
#pragma unroll
            for (int off = 4; off >= 1; off >>= 1) {
                float od = __shfl_down_sync(0xffffffffu, d2, off);
                int   oi = __shfl_down_sync(0xffffffffu, i2, off);
                if (od > d2 || (od == d2 && oi < i2)) { d2 = od; i2 = oi; }
            }
            if (lane == 0) {
                s_cur = i2;
                int g = b * MPTS + step;
                float qx = sp[4*i2], qy = sp[4*i2+1], qz = sp[4*i2+2];
                g_q[3*g] = qx; g_q[3*g+1] = qy; g_q[3*g+2] = qz;
                if (out_size >= BBASE) {
                    dout[PBASE+3*g] = qx; dout[PBASE+3*g+1] = qy; dout[PBASE+3*g+2] = qz;
                }
                if (out_size >= TOTSEG) dout[BBASE+g] = (float)b;
            }
        }
        __syncthreads();
    }
}

// ============================================================================
// 2) Radius + 64 nearest (stable order ala top_k). One warp per centroid.
// ============================================================================
__global__ void __launch_bounds__(256)
nbr_kernel(const float* __restrict__ pos)
{
    extern __shared__ float sm2[];             // sp[NPTS*4] | bufd[8*CAP] | bufi[8*CAP]
    float* sp = sm2;
    const int tid = threadIdx.x, lane = tid & 31, w = tid >> 5;
    const int g = blockIdx.x * 8 + w;
    const int b = (blockIdx.x * 8) / MPTS;     // all 8 warps same cloud
    const float* pb = pos + (size_t)b * NPTS * 3;

    for (int i = tid; i < NPTS * 3; i += 256) {
        int p = i / 3, c = i - 3 * p;
        sp[4 * p + c] = pb[i];
    }
    __syncthreads();

    float* bufd = sm2 + 4 * NPTS + w * CAP;
    int*   bufi = (int*)(sm2 + 4 * NPTS + 8 * CAP) + w * CAP;

    const float qx = g_q[3*g], qy = g_q[3*g+1], qz = g_q[3*g+2];
    const float R2 = (float)(0.15 * 0.15);
    const float4* sp4 = (const float4*)sp;

    int cnt = 0;
    for (int i = lane; i < NPTS; i += 32) {
        float4 p = sp4[i];
        float dx = __fadd_rn(qx, -p.x);
        float dy = __fadd_rn(qy, -p.y);
        float dz = __fadd_rn(qz, -p.z);
        float d2 = __fadd_rn(__fadd_rn(__fmul_rn(dx,dx), __fmul_rn(dy,dy)),
                             __fmul_rn(dz,dz));
        bool keep = (d2 <= R2);
        unsigned msk = __ballot_sync(0xffffffffu, keep);
        if (keep) {
            int ofs = cnt + __popc(msk & ((1u << lane) - 1u));
            if (ofs < CAP) { bufd[ofs] = d2; bufi[ofs] = i; }
        }
        cnt += __popc(msk);
    }
    if (cnt > CAP) cnt = CAP;

    if (cnt <= KNBR) {
        for (int t = lane; t < cnt; t += 32) g_nbr[g*KNBR + t] = bufi[t];
        if (lane == 0) g_cnt[g] = cnt;
    } else {
        for (int t = lane; t < cnt; t += 32) {
            float di = bufd[t]; int ii = bufi[t];
            int r = 0;
            for (int j = 0; j < cnt; j++) {
                float dj = bufd[j];
                r += (int)((dj < di) | ((dj == di) & (bufi[j] < ii)));
            }
            if (r < KNBR) g_nbr[g*KNBR + r] = ii;
        }
        if (lane == 0) g_cnt[g] = KNBR;
    }
}

// ============================================================================
// 3) MLP (67->64->64->128, ReLU) + max over neighbors. Register-tiled GEMMs,
//    weights staged once per block, 8 centroids per block.
// smem floats: W1 4288 | b1 64 | W2 4096 | b2 64 | W3 8192 | b3 128 |
//              feat 64x68 | h1 64x65 | h2 64x65 | red 16x128  = 31552
// ============================================================================
#define SM_W1 0
#define SM_B1 4288
#define SM_W2 4352
#define SM_B2 8448
#define SM_W3 8512
#define SM_B3 16704
#define SM_F  16832
#define SM_H1 21184
#define SM_H2 25344
#define SM_R  29504
#define SM_TOT 31552

__global__ void __launch_bounds__(256)
mlp_kernel(const float* __restrict__ x, const float* __restrict__ pos,
           const float* __restrict__ W1, const float* __restrict__ b1,
           const float* __restrict__ W2, const float* __restrict__ b2,
           const float* __restrict__ W3, const float* __restrict__ b3,
           float* __restrict__ dout, int out_size)
{
    extern __shared__ float sm[];
    const int tid = threadIdx.x;
    for (int i = tid; i < 4288; i += 256) sm[SM_W1 + i] = W1[i];
    for (int i = tid; i < 4096; i += 256) sm[SM_W2 + i] = W2[i];
    for (int i = tid; i < 8192; i += 256) sm[SM_W3 + i] = W3[i];
    if (tid < 64)  { sm[SM_B1 + tid] = b1[tid]; sm[SM_B2 + tid] = b2[tid]; }
    if (tid < 128)   sm[SM_B3 + tid] = b3[tid];
    __syncthreads();

    const int rg = tid >> 4;    // 0..15: rows 4rg..4rg+3 (neighbors)
    const int cg = tid & 15;    // 0..15: col group

    for (int g = blockIdx.x * 8; g < blockIdx.x * 8 + 8; g++) {
        const int b = g / MPTS;
        const int cnt = g_cnt[g];
        const float qx = g_q[3*g], qy = g_q[3*g+1], qz = g_q[3*g+2];

        // build feat [64][68]: x_j(64) || p_j - q (3)
        {
            int e = tid >> 2, part = tid & 3;
            int j = (e < cnt) ? g_nbr[g*KNBR + e] : g_nbr[g*KNBR];
            const float* xr = x + ((size_t)b * NPTS + j) * FDIM;
            for (int k = part; k < 64; k += 4) sm[SM_F + e*68 + k] = xr[k];
            if (part == 0) {
                const float* pr = pos + ((size_t)b * NPTS + j) * 3;
                sm[SM_F + e*68 + 64] = __fadd_rn(pr[0], -qx);
                sm[SM_F + e*68 + 65] = __fadd_rn(pr[1], -qy);
                sm[SM_F + e*68 + 66] = __fadd_rn(pr[2], -qz);
            }
        }
        __syncthreads();

        // layer 1: [64x67]@[67x64]
        {
            float acc[4][4];
#pragma unroll
            for (int i = 0; i < 4; i++)
#pragma unroll
                for (int c = 0; c < 4; c++) acc[i][c] = sm[SM_B1 + 4*cg + c];
            for (int k = 0; k < 67; k++) {
                float4 wv = *(const float4*)(sm + SM_W1 + k*64 + 4*cg);
#pragma unroll
                for (int i = 0; i < 4; i++) {
                    float a = sm[SM_F + (4*rg + i)*68 + k];
                    acc[i][0] = fmaf(a, wv.x, acc[i][0]);
                    acc[i][1] = fmaf(a, wv.y, acc[i][1]);
                    acc[i][2] = fmaf(a, wv.z, acc[i][2]);
                    acc[i][3] = fmaf(a, wv.w, acc[i][3]);
                }
            }
#pragma unroll
            for (int i = 0; i < 4; i++)
#pragma unroll
                for (int c = 0; c < 4; c++)
                    sm[SM_H1 + (4*rg + i)*65 + 4*cg + c] = fmaxf(acc[i][c], 0.0f);
        }
        __syncthreads();

        // layer 2: [64x64]@[64x64]
        {
            float acc[4][4];
#pragma unroll
            for (int i = 0; i < 4; i++)
#pragma unroll
                for (int c = 0; c < 4; c++) acc[i][c] = sm[SM_B2 + 4*cg + c];
            for (int k = 0; k < 64; k++) {
                float4 wv = *(const float4*)(sm + SM_W2 + k*64 + 4*cg);
#pragma unroll
                for (int i = 0; i < 4; i++) {
                    float a = sm[SM_H1 + (4*rg + i)*65 + k];
                    acc[i][0] = fmaf(a, wv.x, acc[i][0]);
                    acc[i][1] = fmaf(a, wv.y, acc[i][1]);
                    acc[i][2] = fmaf(a, wv.z, acc[i][2]);
                    acc[i][3] = fmaf(a, wv.w, acc[i][3]);
                }
            }
#pragma unroll
            for (int i = 0; i < 4; i++)
#pragma unroll
                for (int c = 0; c < 4; c++)
                    sm[SM_H2 + (4*rg + i)*65 + 4*cg + c] = fmaxf(acc[i][c], 0.0f);
        }
        __syncthreads();

        // layer 3: [64x64]@[64x128], then max over own 4 rows
        {
            float acc[4][8];
#pragma unroll
            for (int i = 0; i < 4; i++)
#pragma unroll
                for (int c = 0; c < 8; c++) acc[i][c] = sm[SM_B3 + 8*cg + c];
            for (int k = 0; k < 64; k++) {
                float4 w0 = *(const float4*)(sm + SM_W3 + k*128 + 8*cg);
                float4 w1 = *(const float4*)(sm + SM_W3 + k*128 + 8*cg + 4);
#pragma unroll
                for (int i = 0; i < 4; i++) {
                    float a = sm[SM_H2 + (4*rg + i)*65 + k];
                    acc[i][0] = fmaf(a, w0.x, acc[i][0]);
                    acc[i][1] = fmaf(a, w0.y, acc[i][1]);
                    acc[i][2] = fmaf(a, w0.z, acc[i][2]);
                    acc[i][3] = fmaf(a, w0.w, acc[i][3]);
                    acc[i][4] = fmaf(a, w1.x, acc[i][4]);
                    acc[i][5] = fmaf(a, w1.y, acc[i][5]);
                    acc[i][6] = fmaf(a, w1.z, acc[i][6]);
                    acc[i][7] = fmaf(a, w1.w, acc[i][7]);
                }
            }
#pragma unroll
            for (int c = 0; c < 8; c++) {
                float m = fmaxf(acc[0][c], 0.0f);
#pragma unroll
                for (int i = 1; i < 4; i++) m = fmaxf(m, fmaxf(acc[i][c], 0.0f));
                sm[SM_R + rg*128 + 8*cg + c] = m;
            }
        }
        __syncthreads();

        if (tid < 128) {
            float m = sm[SM_R + tid];
#pragma unroll
            for (int r = 1; r < 16; r++) m = fmaxf(m, sm[SM_R + r*128 + tid]);
            dout[(size_t)g * 128 + tid] = m;
        }
        __syncthreads();
    }
}

// ============================================================================
extern "C" void kernel_launch(void* const* d_in, const int* in_sizes, int n_in,
                              void* d_out, int out_size)
{
    const float* x   = (const float*)d_in[0];
    const float* pos = (const float*)d_in[1];
    // d_in[2] = batch (int64), unused (layout fixed)
    const float* W1 = (const float*)d_in[3];
    const float* b1 = (const float*)d_in[4];
    const float* W2 = (const float*)d_in[5];
    const float* b2 = (const float*)d_in[6];
    const float* W3 = (const float*)d_in[7];
    const float* b3 = (const float*)d_in[8];
    float* out = (float*)d_out;

    const int fps_smem = NPTS * 4 * sizeof(float);                       // 64 KB
    const int nbr_smem = fps_smem + 8 * CAP * 2 * sizeof(float);         // 80 KB
    const int mlp_smem = SM_TOT * sizeof(float);                         // ~123 KB
    cudaFuncSetAttribute(fps_kernel, cudaFuncAttributeMaxDynamicSharedMemorySize, fps_smem);
    cudaFuncSetAttribute(nbr_kernel, cudaFuncAttributeMaxDynamicSharedMemorySize, nbr_smem);
    cudaFuncSetAttribute(mlp_kernel, cudaFuncAttributeMaxDynamicSharedMemorySize, mlp_smem);

    fps_kernel<<<BATCH, 256, fps_smem>>>(pos, out, out_size);
    nbr_kernel<<<NG / 8, 256, nbr_smem>>>(pos);
    mlp_kernel<<<NG / 8, 256, mlp_smem>>>(x, pos, W1, b1, W2, b2, W3, b3, out, out_size);
}